// round 1
// baseline (speedup 1.0000x reference)
#include <cuda_runtime.h>
#include <math.h>

#define BB 64
#define NN 10
#define IC 6912
#define ID 16
#define OD 16
#define JB 48
#define NBLK (IC / JB)   // 144 blocks
#define NTH 640          // tid = n*64 + b

// Scratch (device globals: allocation-free). u_hat layout [j][n][b][o] for coalescing.
__device__ float g_uhat[(size_t)IC * NN * BB * OD];  // 283 MB
__device__ float g_s[BB * NN * OD];                  // s accumulator [b][n][o]
__device__ float g_vsum[BB * NN * OD];               // running sum of v over iters

__global__ void k_zero() {
    int i = blockIdx.x * blockDim.x + threadIdx.x;
    if (i < BB * NN * OD) { g_s[i] = 0.f; g_vsum[i] = 0.f; }
}

// Kernel A: u_hat GEMM (per j: [64x16] @ [16x160]) + fused pass-0 reduction
// (c uniform = 1/10 since b starts at 0).
__global__ __launch_bounds__(NTH) void k_uhat(const float* __restrict__ x,
                                              const float* __restrict__ W) {
    __shared__ float xs[BB * 17];                      // padded: conflict-free
    __shared__ __align__(16) float ws[NN * ID * OD];   // [n][i*16+o]
    const int tid = threadIdx.x;
    const int n = tid >> 6;
    const int b = tid & 63;
    const int j0 = blockIdx.x * JB;

    float s_acc[OD];
#pragma unroll
    for (int o = 0; o < OD; o++) s_acc[o] = 0.f;

    for (int jj = 0; jj < JB; jj++) {
        const int j = j0 + jj;
        // stage x[:, j, :] (64x16) and W[:, j, :, :] (10x16x16)
        for (int t = tid; t < BB * ID; t += NTH)
            xs[(t >> 4) * 17 + (t & 15)] = x[((t >> 4) * IC + j) * ID + (t & 15)];
        for (int t = tid; t < NN * ID * OD; t += NTH)
            ws[t] = W[((size_t)(t >> 8) * IC + j) * (ID * OD) + (t & 255)];
        __syncthreads();

        float u[OD];
#pragma unroll
        for (int o = 0; o < OD; o++) u[o] = 0.f;
        const float* wn = ws + n * (ID * OD);
#pragma unroll
        for (int i = 0; i < ID; i++) {
            float xv = xs[b * 17 + i];
            const float4* w4 = (const float4*)(wn + i * OD);  // warp-uniform -> broadcast
            float4 wa = w4[0], wb = w4[1], wc = w4[2], wd = w4[3];
            u[0]  = fmaf(xv, wa.x, u[0]);  u[1]  = fmaf(xv, wa.y, u[1]);
            u[2]  = fmaf(xv, wa.z, u[2]);  u[3]  = fmaf(xv, wa.w, u[3]);
            u[4]  = fmaf(xv, wb.x, u[4]);  u[5]  = fmaf(xv, wb.y, u[5]);
            u[6]  = fmaf(xv, wb.z, u[6]);  u[7]  = fmaf(xv, wb.w, u[7]);
            u[8]  = fmaf(xv, wc.x, u[8]);  u[9]  = fmaf(xv, wc.y, u[9]);
            u[10] = fmaf(xv, wc.z, u[10]); u[11] = fmaf(xv, wc.w, u[11]);
            u[12] = fmaf(xv, wd.x, u[12]); u[13] = fmaf(xv, wd.y, u[13]);
            u[14] = fmaf(xv, wd.z, u[14]); u[15] = fmaf(xv, wd.w, u[15]);
        }
        // coalesced store: [j][n][b][o]
        float4* dst = (float4*)(g_uhat + (((size_t)j * NN + n) * BB + b) * OD);
        dst[0] = make_float4(u[0], u[1], u[2], u[3]);
        dst[1] = make_float4(u[4], u[5], u[6], u[7]);
        dst[2] = make_float4(u[8], u[9], u[10], u[11]);
        dst[3] = make_float4(u[12], u[13], u[14], u[15]);
#pragma unroll
        for (int o = 0; o < OD; o++) s_acc[o] += u[o];
        __syncthreads();
    }
    float* sp = g_s + (b * NN + n) * OD;
#pragma unroll
    for (int o = 0; o < OD; o++) atomicAdd(sp + o, 0.1f * s_acc[o]);
}

// Kernel B: squash s -> v. Non-final: vsum += v, s = 0. Final: write output.
__global__ void k_squash(float* __restrict__ out, int final_pass) {
    int t = threadIdx.x;
    if (t >= BB * NN) return;
    float4* sp = (float4*)(g_s + t * OD);
    float4 a = sp[0], b4 = sp[1], c4 = sp[2], d4 = sp[3];
    float s[OD] = {a.x, a.y, a.z, a.w, b4.x, b4.y, b4.z, b4.w,
                   c4.x, c4.y, c4.z, c4.w, d4.x, d4.y, d4.z, d4.w};
    float s2 = 0.f;
#pragma unroll
    for (int o = 0; o < OD; o++) s2 = fmaf(s[o], s[o], s2);
    float scale = (s2 / (1.f + s2)) * rsqrtf(s2 + 1e-7f);
    if (final_pass) {
        float4* op = (float4*)(out + t * OD);
        op[0] = make_float4(scale * s[0], scale * s[1], scale * s[2], scale * s[3]);
        op[1] = make_float4(scale * s[4], scale * s[5], scale * s[6], scale * s[7]);
        op[2] = make_float4(scale * s[8], scale * s[9], scale * s[10], scale * s[11]);
        op[3] = make_float4(scale * s[12], scale * s[13], scale * s[14], scale * s[15]);
    } else {
        float* vp = g_vsum + t * OD;
#pragma unroll
        for (int o = 0; o < OD; o++) vp[o] += scale * s[o];
        float4 z = make_float4(0.f, 0.f, 0.f, 0.f);
        sp[0] = z; sp[1] = z; sp[2] = z; sp[3] = z;
    }
}

// Kernel C: one routing pass. Logits on-the-fly: d = u_hat . vsum (vsum in regs,
// fixed (b,n) per thread), softmax over n via smem exchange, accumulate s.
__global__ __launch_bounds__(NTH) void k_route() {
    __shared__ float es[2][NN][BB];
    const int tid = threadIdx.x;
    const int n = tid >> 6;
    const int b = tid & 63;
    const int j0 = blockIdx.x * JB;

    float vs[OD];
    {
        const float4* vp = (const float4*)(g_vsum + (b * NN + n) * OD);
#pragma unroll
        for (int k = 0; k < 4; k++) {
            float4 v = vp[k];
            vs[4 * k] = v.x; vs[4 * k + 1] = v.y; vs[4 * k + 2] = v.z; vs[4 * k + 3] = v.w;
        }
    }
    float s_acc[OD];
#pragma unroll
    for (int o = 0; o < OD; o++) s_acc[o] = 0.f;

    for (int jj = 0; jj < JB; jj++) {
        const int j = j0 + jj;
        const float4* up = (const float4*)(g_uhat + (((size_t)j * NN + n) * BB + b) * OD);
        float4 u0 = up[0], u1 = up[1], u2 = up[2], u3 = up[3];
        float u[OD] = {u0.x, u0.y, u0.z, u0.w, u1.x, u1.y, u1.z, u1.w,
                       u2.x, u2.y, u2.z, u2.w, u3.x, u3.y, u3.z, u3.w};
        float d = 0.f;
#pragma unroll
        for (int o = 0; o < OD; o++) d = fmaf(u[o], vs[o], d);
        float e = __expf(d);  // |d| small; no max-subtraction needed in fp32
        es[jj & 1][n][b] = e;
        __syncthreads();
        float sum = 0.f;
#pragma unroll
        for (int m = 0; m < NN; m++) sum += es[jj & 1][m][b];
        float c = e / sum;
#pragma unroll
        for (int o = 0; o < OD; o++) s_acc[o] = fmaf(c, u[o], s_acc[o]);
    }
    float* sp = g_s + (b * NN + n) * OD;
#pragma unroll
    for (int o = 0; o < OD; o++) atomicAdd(sp + o, s_acc[o]);
}

extern "C" void kernel_launch(void* const* d_in, const int* in_sizes, int n_in,
                              void* d_out, int out_size) {
    const float* x = (const float*)d_in[0];  // [64, 6912, 16]
    const float* W = (const float*)d_in[1];  // [10, 6912, 16, 16]
    float* out = (float*)d_out;              // [64, 10, 16]

    k_zero<<<(BB * NN * OD + 255) / 256, 256>>>();
    k_uhat<<<NBLK, NTH>>>(x, W);      // u_hat + fused s0 (uniform c)
    k_squash<<<1, NTH>>>(out, 0);     // v0; vsum = v0
    k_route<<<NBLK, NTH>>>();         // s1 with logits b1 = u_hat . v0
    k_squash<<<1, NTH>>>(out, 0);     // v1; vsum = v0 + v1
    k_route<<<NBLK, NTH>>>();         // s2 with logits b2 = u_hat . (v0+v1)
    k_squash<<<1, NTH>>>(out, 1);     // v2 -> output
}

// round 2
// speedup vs baseline: 1.4772x; 1.4772x over previous
#include <cuda_runtime.h>
#include <cuda_fp16.h>
#include <math.h>

#define BB 64
#define NN 10
#define ID 16
#define OD 16
#define IC 6912
#define JB 48          // j-tile for k_uhat
#define NTH 640        // k_uhat: tid = n*64 + b
#define RT_JB 48       // j-tile for k_route
#define RT_TH 256      // k_route: tid = g*16 + n  (16 b's per block)

// Packed f32x2 helpers (sm_100+ PTX)
#define FFMA2(d, a, b) asm("fma.rn.f32x2 %0, %1, %2, %0;" : "+l"(d) : "l"(a), "l"(b))
#define FADD2(d, a)    asm("add.rn.f32x2 %0, %0, %1;"     : "+l"(d) : "l"(a))

// Scratch (device globals: allocation-free).
// u_hat fp16, layout [j][b][n][o]; +128 pad for the n=10..15 ghost-lane reads.
__device__ __half g_uhat[(size_t)IC * BB * NN * OD + 128];
__device__ float g_s[BB * NN * OD];     // s accumulator [b][n][o]
__device__ float g_vsum[BB * NN * OD];  // running sum of v over iterations

__global__ void k_zero() {
    int i = blockIdx.x * blockDim.x + threadIdx.x;
    if (i < BB * NN * OD) { g_s[i] = 0.f; g_vsum[i] = 0.f; }
}

// ───────────────────────────── Kernel A: u_hat GEMM ─────────────────────────
// Per j: [64x16] @ [16x160]. Double-buffered smem (1 barrier/iter), register-
// staged prefetch, packed f32x2 FMA. Fused pass-0 reduction (c uniform = 0.1).
__global__ __launch_bounds__(NTH) void k_uhat(const float* __restrict__ x,
                                              const float* __restrict__ W) {
    __shared__ float xs[2][BB * 17];                     // padded, conflict-free
    __shared__ __align__(16) float ws[2][NN * ID * OD];  // [n][i*16+o]
    const int tid = threadIdx.x;
    const int n = tid >> 6;
    const int b = tid & 63;
    const int j0 = blockIdx.x * JB;

    float wr[4], xr[2];
    // ── prolog: load j0, fill buffer 0 ──
    {
        const int j = j0;
#pragma unroll
        for (int k = 0; k < 4; k++) {
            int e = tid + k * NTH;  // 2560 W floats
            wr[k] = W[((size_t)(e >> 8) * IC + j) * 256 + (e & 255)];
        }
        if (tid < 512) {
#pragma unroll
            for (int k = 0; k < 2; k++) {
                int e = tid + k * 512;  // 1024 x floats
                xr[k] = x[((size_t)(e >> 4) * IC + j) * 16 + (e & 15)];
            }
        }
#pragma unroll
        for (int k = 0; k < 4; k++) ws[0][tid + k * NTH] = wr[k];
        if (tid < 512) {
#pragma unroll
            for (int k = 0; k < 2; k++) {
                int e = tid + k * 512;
                xs[0][(e >> 4) * 17 + (e & 15)] = xr[k];
            }
        }
    }

    unsigned long long s2[8];  // packed fp32x2 pass-0 accumulators
#pragma unroll
    for (int k = 0; k < 8; k++) s2[k] = 0ull;

    for (int jj = 0; jj < JB; jj++) {
        const int cur = jj & 1;
        __syncthreads();  // buf[cur] ready; prior reads of buf[cur^1] done

        // issue prefetch LDGs for j+1 (in flight during compute)
        if (jj + 1 < JB) {
            const int j = j0 + jj + 1;
#pragma unroll
            for (int k = 0; k < 4; k++) {
                int e = tid + k * NTH;
                wr[k] = W[((size_t)(e >> 8) * IC + j) * 256 + (e & 255)];
            }
            if (tid < 512) {
#pragma unroll
                for (int k = 0; k < 2; k++) {
                    int e = tid + k * 512;
                    xr[k] = x[((size_t)(e >> 4) * IC + j) * 16 + (e & 15)];
                }
            }
        }

        // ── compute u[16] for this thread's (b, n, j) ──
        unsigned long long u2[8];
#pragma unroll
        for (int k = 0; k < 8; k++) u2[k] = 0ull;
        const float* xrow = xs[cur] + b * 17;
        const ulonglong2* wbase = (const ulonglong2*)(ws[cur] + n * 256);  // warp-uniform
#pragma unroll
        for (int i = 0; i < ID; i++) {
            float xv = xrow[i];
            unsigned long long xv2;
            asm("mov.b64 %0, {%1, %1};" : "=l"(xv2) : "f"(xv));
            ulonglong2 p0 = wbase[i * 4 + 0], p1 = wbase[i * 4 + 1];
            ulonglong2 p2 = wbase[i * 4 + 2], p3 = wbase[i * 4 + 3];
            FFMA2(u2[0], xv2, p0.x); FFMA2(u2[1], xv2, p0.y);
            FFMA2(u2[2], xv2, p1.x); FFMA2(u2[3], xv2, p1.y);
            FFMA2(u2[4], xv2, p2.x); FFMA2(u2[5], xv2, p2.y);
            FFMA2(u2[6], xv2, p3.x); FFMA2(u2[7], xv2, p3.y);
        }

        // store fp16 u_hat [j][b][n][o] (each lane: one full 32B sector)
        {
            const int j = j0 + jj;
            __align__(16) __half2 h[8];
#pragma unroll
            for (int k = 0; k < 8; k++) {
                float lo, hi;
                asm("mov.b64 {%0, %1}, %2;" : "=f"(lo), "=f"(hi) : "l"(u2[k]));
                h[k] = __floats2half2_rn(lo, hi);
            }
            uint4* dst = (uint4*)(g_uhat + ((size_t)(j * BB + b) * NN + n) * OD);
            dst[0] = *(uint4*)&h[0];
            dst[1] = *(uint4*)&h[4];
#pragma unroll
            for (int k = 0; k < 8; k++) FADD2(s2[k], u2[k]);
        }

        __syncthreads();  // everyone done reading buf[cur] before it's refilled
        if (jj + 1 < JB) {
            const int nb = (jj + 1) & 1;
#pragma unroll
            for (int k = 0; k < 4; k++) ws[nb][tid + k * NTH] = wr[k];
            if (tid < 512) {
#pragma unroll
                for (int k = 0; k < 2; k++) {
                    int e = tid + k * 512;
                    xs[nb][(e >> 4) * 17 + (e & 15)] = xr[k];
                }
            }
        }
    }

    float* sp = g_s + (b * NN + n) * OD;
#pragma unroll
    for (int k = 0; k < 8; k++) {
        float lo, hi;
        asm("mov.b64 {%0, %1}, %2;" : "=f"(lo), "=f"(hi) : "l"(s2[k]));
        atomicAdd(sp + 2 * k, 0.1f * lo);
        atomicAdd(sp + 2 * k + 1, 0.1f * hi);
    }
}

// ───────────────────────── Kernel B: squash s -> v ──────────────────────────
__global__ void k_squash(float* __restrict__ out, int final_pass) {
    int t = threadIdx.x;
    if (t >= BB * NN) return;
    float4* sp = (float4*)(g_s + t * OD);
    float4 a = sp[0], b4 = sp[1], c4 = sp[2], d4 = sp[3];
    float s[OD] = {a.x, a.y, a.z, a.w, b4.x, b4.y, b4.z, b4.w,
                   c4.x, c4.y, c4.z, c4.w, d4.x, d4.y, d4.z, d4.w};
    float s2 = 0.f;
#pragma unroll
    for (int o = 0; o < OD; o++) s2 = fmaf(s[o], s[o], s2);
    float scale = (s2 / (1.f + s2)) * rsqrtf(s2 + 1e-7f);
    if (final_pass) {
        float4* op = (float4*)(out + t * OD);
        op[0] = make_float4(scale * s[0], scale * s[1], scale * s[2], scale * s[3]);
        op[1] = make_float4(scale * s[4], scale * s[5], scale * s[6], scale * s[7]);
        op[2] = make_float4(scale * s[8], scale * s[9], scale * s[10], scale * s[11]);
        op[3] = make_float4(scale * s[12], scale * s[13], scale * s[14], scale * s[15]);
    } else {
        float* vp = g_vsum + t * OD;
#pragma unroll
        for (int o = 0; o < OD; o++) vp[o] += scale * s[o];
        float4 z = make_float4(0.f, 0.f, 0.f, 0.f);
        sp[0] = z; sp[1] = z; sp[2] = z; sp[3] = z;
    }
}

// ───────────────────────── Kernel C: routing pass ───────────────────────────
// Barrier-free: 16-lane groups hold all n for one (b, j); softmax via shfl.xor
// width 16. Logits on-the-fly: d = u_hat . vsum (vsum in regs). Depth-1 LDG
// prefetch. Lanes n=10..15 idle (e=0), reads land in the +128 pad.
__global__ __launch_bounds__(RT_TH, 3) void k_route() {
    const int tid = threadIdx.x;
    const int n = tid & 15;
    const int b = blockIdx.y * 16 + (tid >> 4);
    const int j0 = blockIdx.x * RT_JB;

    float vs[OD];
    {
        int nc = (n < NN) ? n : (NN - 1);
        const float4* vp = (const float4*)(g_vsum + (b * NN + nc) * OD);
#pragma unroll
        for (int k = 0; k < 4; k++) {
            float4 v = vp[k];
            vs[4 * k] = v.x; vs[4 * k + 1] = v.y;
            vs[4 * k + 2] = v.z; vs[4 * k + 3] = v.w;
        }
    }
    float s_acc[OD];
#pragma unroll
    for (int o = 0; o < OD; o++) s_acc[o] = 0.f;

    const uint4* up = (const uint4*)(g_uhat + ((size_t)(j0 * BB + b) * NN + n) * OD);
    const int step = (BB * NN * OD) / 8;  // uint4 stride per j
    uint4 pA = up[0], pB = up[1];

    for (int jj = 0; jj < RT_JB; jj++) {
        uint4 cA = pA, cB = pB;
        if (jj + 1 < RT_JB) {
            const uint4* nx = up + (size_t)(jj + 1) * step;
            pA = nx[0]; pB = nx[1];
        }
        float u[OD];
        {
            const __half2* hA = (const __half2*)&cA;
            const __half2* hB = (const __half2*)&cB;
#pragma unroll
            for (int k = 0; k < 4; k++) {
                float2 f = __half22float2(hA[k]);
                u[2 * k] = f.x; u[2 * k + 1] = f.y;
            }
#pragma unroll
            for (int k = 0; k < 4; k++) {
                float2 f = __half22float2(hB[k]);
                u[8 + 2 * k] = f.x; u[8 + 2 * k + 1] = f.y;
            }
        }
        float d = 0.f;
#pragma unroll
        for (int o = 0; o < OD; o++) d = fmaf(u[o], vs[o], d);
        float e = (n < NN) ? __expf(d) : 0.f;  // |d| small: no max-shift needed
        float sum = e;
#pragma unroll
        for (int m = 1; m < 16; m <<= 1)
            sum += __shfl_xor_sync(0xFFFFFFFFu, sum, m, 16);
        float c = __fdividef(e, sum);
#pragma unroll
        for (int o = 0; o < OD; o++) s_acc[o] = fmaf(c, u[o], s_acc[o]);
    }

    if (n < NN) {
        float* sp = g_s + (b * NN + n) * OD;
#pragma unroll
        for (int o = 0; o < OD; o++) atomicAdd(sp + o, s_acc[o]);
    }
}

extern "C" void kernel_launch(void* const* d_in, const int* in_sizes, int n_in,
                              void* d_out, int out_size) {
    const float* x = (const float*)d_in[0];  // [64, 6912, 16]
    const float* W = (const float*)d_in[1];  // [10, 6912, 16, 16]
    float* out = (float*)d_out;              // [64, 10, 16]

    dim3 rgrid(IC / RT_JB, BB / 16);

    k_zero<<<(BB * NN * OD + 255) / 256, 256>>>();
    k_uhat<<<IC / JB, NTH>>>(x, W);   // u_hat (fp16) + fused s0 (uniform c)
    k_squash<<<1, NTH>>>(out, 0);     // v0; vsum = v0
    k_route<<<rgrid, RT_TH>>>();      // s1, logits = u_hat . v0
    k_squash<<<1, NTH>>>(out, 0);     // v1; vsum = v0 + v1
    k_route<<<rgrid, RT_TH>>>();      // s2, logits = u_hat . (v0+v1)
    k_squash<<<1, NTH>>>(out, 1);     // v2 -> output
}

// round 3
// speedup vs baseline: 1.5380x; 1.0412x over previous
#include <cuda_runtime.h>
#include <cuda_fp16.h>
#include <math.h>

#define BB 64
#define NN 10
#define ID 16
#define OD 16
#define IC 6912
#define JB 24          // j-tile for k_uhat (grid 288 -> 2 blocks/SM)
#define NTH 320        // k_uhat: tid = n*32 + bp; thread owns b=2bp, 2bp+1
#define RT_JB 48       // j-tile for k_route (multiple of 3)
#define RT_TH 256      // k_route: tid = g*16 + n  (16 b's per block)

// Packed f32x2 helpers (sm_100+ PTX)
#define FFMA2(d, a, b) asm("fma.rn.f32x2 %0, %1, %2, %0;" : "+l"(d) : "l"(a), "l"(b))
#define FADD2(d, a)    asm("add.rn.f32x2 %0, %0, %1;"     : "+l"(d) : "l"(a))

// Scratch (device globals: allocation-free).
// u_hat fp16, layout [j][b][n][o]; +128 pad for the n=10..15 ghost-lane reads.
__device__ __half g_uhat[(size_t)IC * BB * NN * OD + 128];
__device__ float g_s[BB * NN * OD];     // s accumulator [b][n][o]
__device__ float g_vsum[BB * NN * OD];  // running sum of v over iterations

__global__ void k_zero() {
    int i = blockIdx.x * blockDim.x + threadIdx.x;
    if (i < BB * NN * OD) { g_s[i] = 0.f; g_vsum[i] = 0.f; }
}

// ───────────────────────────── Kernel A: u_hat GEMM ─────────────────────────
// Per j: [64x16] @ [16x160]. Thread = (n, b-pair): halves LDS per FFMA2 vs
// 1-b mapping. Double-buffered smem, register-staged prefetch, f32x2 FMA.
// Fused pass-0 reduction (b=0 -> c uniform = 0.1).
__global__ __launch_bounds__(NTH) void k_uhat(const float* __restrict__ x,
                                              const float* __restrict__ W) {
    __shared__ float xs[2][BB * ID];                     // [i*64 + b]
    __shared__ __align__(16) float ws[2][NN * ID * OD];  // [n*256 + i*16 + o]
    const int tid = threadIdx.x;
    const int n = tid >> 5;       // warp == one n
    const int bp = tid & 31;
    const int b0 = 2 * bp;
    const int j0 = blockIdx.x * JB;

    uint4 wr[2];
    float xr[4];

    // prolog: load + stage j0 into buffer 0
    {
        const int j = j0;
#pragma unroll
        for (int k = 0; k < 2; k++) {
            int f = (tid + k * NTH) * 4;
            wr[k] = *(const uint4*)(W + ((size_t)(f >> 8) * IC + j) * 256 + (f & 255));
        }
#pragma unroll
        for (int k = 0; k < 4; k++) {
            int e = tid + k * NTH;
            if (e < BB * ID) xr[k] = x[((size_t)(e & 63) * IC + j) * ID + (e >> 6)];
        }
#pragma unroll
        for (int k = 0; k < 2; k++) ((uint4*)ws[0])[tid + k * NTH] = wr[k];
#pragma unroll
        for (int k = 0; k < 4; k++) {
            int e = tid + k * NTH;
            if (e < BB * ID) xs[0][(e >> 6) * 64 + (e & 63)] = xr[k];
        }
    }

    unsigned long long s2a[8], s2b[8];  // pass-0 accumulators (per b)
#pragma unroll
    for (int k = 0; k < 8; k++) { s2a[k] = 0ull; s2b[k] = 0ull; }

    for (int jj = 0; jj < JB; jj++) {
        const int cur = jj & 1;
        __syncthreads();  // buf[cur] ready; prior reads of buf[cur^1] done

        if (jj + 1 < JB) {  // prefetch LDGs for j+1 (in flight during compute)
            const int j = j0 + jj + 1;
#pragma unroll
            for (int k = 0; k < 2; k++) {
                int f = (tid + k * NTH) * 4;
                wr[k] = *(const uint4*)(W + ((size_t)(f >> 8) * IC + j) * 256 + (f & 255));
            }
#pragma unroll
            for (int k = 0; k < 4; k++) {
                int e = tid + k * NTH;
                if (e < BB * ID) xr[k] = x[((size_t)(e & 63) * IC + j) * ID + (e >> 6)];
            }
        }

        // compute u[16] for (b0, n, j) and (b0+1, n, j)
        unsigned long long u2a[8], u2b[8];
#pragma unroll
        for (int k = 0; k < 8; k++) { u2a[k] = 0ull; u2b[k] = 0ull; }
        const ulonglong2* wb = (const ulonglong2*)(ws[cur] + n * 256);  // warp-uniform
        const float* xrow = xs[cur];
#pragma unroll
        for (int i = 0; i < ID; i++) {
            float2 xv = *(const float2*)(xrow + i * 64 + b0);
            unsigned long long xa2, xb2;
            asm("mov.b64 %0, {%1, %1};" : "=l"(xa2) : "f"(xv.x));
            asm("mov.b64 %0, {%1, %1};" : "=l"(xb2) : "f"(xv.y));
            ulonglong2 p0 = wb[i * 4 + 0], p1 = wb[i * 4 + 1];
            ulonglong2 p2 = wb[i * 4 + 2], p3 = wb[i * 4 + 3];
            FFMA2(u2a[0], xa2, p0.x); FFMA2(u2a[1], xa2, p0.y);
            FFMA2(u2a[2], xa2, p1.x); FFMA2(u2a[3], xa2, p1.y);
            FFMA2(u2a[4], xa2, p2.x); FFMA2(u2a[5], xa2, p2.y);
            FFMA2(u2a[6], xa2, p3.x); FFMA2(u2a[7], xa2, p3.y);
            FFMA2(u2b[0], xb2, p0.x); FFMA2(u2b[1], xb2, p0.y);
            FFMA2(u2b[2], xb2, p1.x); FFMA2(u2b[3], xb2, p1.y);
            FFMA2(u2b[4], xb2, p2.x); FFMA2(u2b[5], xb2, p2.y);
            FFMA2(u2b[6], xb2, p3.x); FFMA2(u2b[7], xb2, p3.y);
        }

        // store fp16 u_hat [j][b][n][o]
        {
            const int j = j0 + jj;
            __align__(16) __half2 ha[8], hb[8];
#pragma unroll
            for (int k = 0; k < 8; k++) {
                float lo, hi;
                asm("mov.b64 {%0, %1}, %2;" : "=f"(lo), "=f"(hi) : "l"(u2a[k]));
                ha[k] = __floats2half2_rn(lo, hi);
                asm("mov.b64 {%0, %1}, %2;" : "=f"(lo), "=f"(hi) : "l"(u2b[k]));
                hb[k] = __floats2half2_rn(lo, hi);
            }
            uint4* da = (uint4*)(g_uhat + ((size_t)(j * BB + b0) * NN + n) * OD);
            uint4* db = (uint4*)(g_uhat + ((size_t)(j * BB + b0 + 1) * NN + n) * OD);
            da[0] = *(uint4*)&ha[0]; da[1] = *(uint4*)&ha[4];
            db[0] = *(uint4*)&hb[0]; db[1] = *(uint4*)&hb[4];
#pragma unroll
            for (int k = 0; k < 8; k++) { FADD2(s2a[k], u2a[k]); FADD2(s2b[k], u2b[k]); }
        }

        __syncthreads();  // all reads of buf[cur] done before refill
        if (jj + 1 < JB) {
            const int nb = (jj + 1) & 1;
#pragma unroll
            for (int k = 0; k < 2; k++) ((uint4*)ws[nb])[tid + k * NTH] = wr[k];
#pragma unroll
            for (int k = 0; k < 4; k++) {
                int e = tid + k * NTH;
                if (e < BB * ID) xs[nb][(e >> 6) * 64 + (e & 63)] = xr[k];
            }
        }
    }

    float* spa = g_s + (b0 * NN + n) * OD;
    float* spb = g_s + ((b0 + 1) * NN + n) * OD;
#pragma unroll
    for (int k = 0; k < 8; k++) {
        float lo, hi;
        asm("mov.b64 {%0, %1}, %2;" : "=f"(lo), "=f"(hi) : "l"(s2a[k]));
        atomicAdd(spa + 2 * k, 0.1f * lo);
        atomicAdd(spa + 2 * k + 1, 0.1f * hi);
        asm("mov.b64 {%0, %1}, %2;" : "=f"(lo), "=f"(hi) : "l"(s2b[k]));
        atomicAdd(spb + 2 * k, 0.1f * lo);
        atomicAdd(spb + 2 * k + 1, 0.1f * hi);
    }
}

// ───────────────────────── Kernel B: squash s -> v ──────────────────────────
__global__ void k_squash(float* __restrict__ out, int final_pass) {
    int t = threadIdx.x;
    if (t >= BB * NN) return;
    float4* sp = (float4*)(g_s + t * OD);
    float4 a = sp[0], b4 = sp[1], c4 = sp[2], d4 = sp[3];
    float s[OD] = {a.x, a.y, a.z, a.w, b4.x, b4.y, b4.z, b4.w,
                   c4.x, c4.y, c4.z, c4.w, d4.x, d4.y, d4.z, d4.w};
    float s2 = 0.f;
#pragma unroll
    for (int o = 0; o < OD; o++) s2 = fmaf(s[o], s[o], s2);
    float scale = (s2 / (1.f + s2)) * rsqrtf(s2 + 1e-7f);
    if (final_pass) {
        float4* op = (float4*)(out + t * OD);
        op[0] = make_float4(scale * s[0], scale * s[1], scale * s[2], scale * s[3]);
        op[1] = make_float4(scale * s[4], scale * s[5], scale * s[6], scale * s[7]);
        op[2] = make_float4(scale * s[8], scale * s[9], scale * s[10], scale * s[11]);
        op[3] = make_float4(scale * s[12], scale * s[13], scale * s[14], scale * s[15]);
    } else {
        float* vp = g_vsum + t * OD;
#pragma unroll
        for (int o = 0; o < OD; o++) vp[o] += scale * s[o];
        float4 z = make_float4(0.f, 0.f, 0.f, 0.f);
        sp[0] = z; sp[1] = z; sp[2] = z; sp[3] = z;
    }
}

// ───────────────────────── Kernel C: routing pass ───────────────────────────
// Barrier-free; 16-lane groups hold all n for one (b, j); softmax via width-16
// shfl.xor. Depth-3 register prefetch pipeline hides DRAM latency. d-dot split
// into 4 chains. Lanes n=10..15: e=0, reads land in pad.
__global__ __launch_bounds__(RT_TH) void k_route() {
    const int tid = threadIdx.x;
    const int n = tid & 15;
    const int b = blockIdx.y * 16 + (tid >> 4);
    const int j0 = blockIdx.x * RT_JB;

    float vs[OD];
    {
        int nc = (n < NN) ? n : (NN - 1);
        const float4* vp = (const float4*)(g_vsum + (b * NN + nc) * OD);
#pragma unroll
        for (int k = 0; k < 4; k++) {
            float4 v = vp[k];
            vs[4 * k] = v.x; vs[4 * k + 1] = v.y;
            vs[4 * k + 2] = v.z; vs[4 * k + 3] = v.w;
        }
    }
    float s_acc[OD];
#pragma unroll
    for (int o = 0; o < OD; o++) s_acc[o] = 0.f;

    const uint4* up = (const uint4*)(g_uhat + ((size_t)(j0 * BB + b) * NN + n) * OD);
    const size_t step = (BB * NN * OD) / 8;  // uint4 stride per j

    uint4 pf[3][2];  // depth-3 pipeline
#pragma unroll
    for (int k = 0; k < 3; k++) {
        const uint4* p = up + (size_t)k * step;
        pf[k][0] = p[0]; pf[k][1] = p[1];
    }

    for (int jo = 0; jo < RT_JB; jo += 3) {
#pragma unroll
        for (int sl = 0; sl < 3; sl++) {
            const int jj = jo + sl;
            uint4 cA = pf[sl][0], cB = pf[sl][1];
            if (jj + 3 < RT_JB) {
                const uint4* nx = up + (size_t)(jj + 3) * step;
                pf[sl][0] = nx[0]; pf[sl][1] = nx[1];
            }
            float u[OD];
            {
                const __half2* hA = (const __half2*)&cA;
                const __half2* hB = (const __half2*)&cB;
#pragma unroll
                for (int k = 0; k < 4; k++) {
                    float2 f = __half22float2(hA[k]);
                    u[2 * k] = f.x; u[2 * k + 1] = f.y;
                }
#pragma unroll
                for (int k = 0; k < 4; k++) {
                    float2 f = __half22float2(hB[k]);
                    u[8 + 2 * k] = f.x; u[8 + 2 * k + 1] = f.y;
                }
            }
            // 4 parallel partial dot chains
            float d0 = 0.f, d1 = 0.f, d2 = 0.f, d3 = 0.f;
#pragma unroll
            for (int k = 0; k < 4; k++) {
                d0 = fmaf(u[k], vs[k], d0);
                d1 = fmaf(u[4 + k], vs[4 + k], d1);
                d2 = fmaf(u[8 + k], vs[8 + k], d2);
                d3 = fmaf(u[12 + k], vs[12 + k], d3);
            }
            float d = (d0 + d1) + (d2 + d3);
            float e = (n < NN) ? __expf(d) : 0.f;  // |d| small: no max-shift
            float sum = e;
#pragma unroll
            for (int m = 1; m < 16; m <<= 1)
                sum += __shfl_xor_sync(0xFFFFFFFFu, sum, m, 16);
            float c = __fdividef(e, sum);
#pragma unroll
            for (int o = 0; o < OD; o++) s_acc[o] = fmaf(c, u[o], s_acc[o]);
        }
    }

    if (n < NN) {
        float* sp = g_s + (b * NN + n) * OD;
#pragma unroll
        for (int o = 0; o < OD; o++) atomicAdd(sp + o, s_acc[o]);
    }
}

extern "C" void kernel_launch(void* const* d_in, const int* in_sizes, int n_in,
                              void* d_out, int out_size) {
    const float* x = (const float*)d_in[0];  // [64, 6912, 16]
    const float* W = (const float*)d_in[1];  // [10, 6912, 16, 16]
    float* out = (float*)d_out;              // [64, 10, 16]

    dim3 rgrid(IC / RT_JB, BB / 16);

    k_zero<<<(BB * NN * OD + 255) / 256, 256>>>();
    k_uhat<<<IC / JB, NTH>>>(x, W);   // u_hat (fp16) + fused s0 (uniform c)
    k_squash<<<1, 640>>>(out, 0);     // v0; vsum = v0
    k_route<<<rgrid, RT_TH>>>();      // s1, logits = u_hat . v0
    k_squash<<<1, 640>>>(out, 0);     // v1; vsum = v0 + v1
    k_route<<<rgrid, RT_TH>>>();      // s2, logits = u_hat . (v0+v1)
    k_squash<<<1, 640>>>(out, 1);     // v2 -> output
}